// round 13
// baseline (speedup 1.0000x reference)
#include <cuda_runtime.h>
#include <cuda_bf16.h>
#include <cuda_fp16.h>
#include <math.h>
#include <stdint.h>

#define B_   2
#define T_   2048
#define H_   16
#define DH   64
#define DL   32
#define CDIM 1024

#define Y_ELEMS  ((size_t)B_*T_*CDIM)
#define KL_ELEMS ((size_t)B_*T_*H_*DL)

// q pre-scale: (1/sqrt(64)) * log2(e)  -> softmax done in log2 domain
#define QSCALE 0.1803368801111204f

// ---- scratch ----
__device__ float g_cos[T_*DH];
__device__ float g_sin[T_*DH];

__device__ __half g_xf[(size_t)B_*T_*CDIM];
__device__ __half g_yf[(size_t)B_*T_*CDIM];
__device__ __half g_qf[(size_t)B_*T_*H_*DH];
__device__ __half g_kf[(size_t)B_*T_*H_*DH];
__device__ __half g_vf[(size_t)B_*T_*H_*DH];
__device__ __half g_wf[3u*1024*1024];
#define WQ_OFF 0u
#define WK_OFF (1024u*1024u)
#define WV_OFF (1536u*1024u)
#define WC_OFF (2048u*1024u)

// ============================================================
// PTX helpers
// ============================================================
__device__ __forceinline__ uint32_t smem_u32(const void* p) {
    uint32_t a;
    asm("{ .reg .u64 t; cvta.to.shared.u64 t, %1; cvt.u32.u64 %0, t; }"
        : "=r"(a) : "l"(p));
    return a;
}
__device__ __forceinline__ void cp16(uint32_t dst, const void* src) {
    asm volatile("cp.async.cg.shared.global [%0], [%1], 16;\n"
                 :: "r"(dst), "l"(src));
}
__device__ __forceinline__ void cp_commit() {
    asm volatile("cp.async.commit_group;\n" ::: "memory");
}
template<int N> __device__ __forceinline__ void cp_wait() {
    asm volatile("cp.async.wait_group %0;\n" :: "n"(N) : "memory");
}
__device__ __forceinline__ void ldm_x4(uint32_t* r, uint32_t addr) {
    asm volatile("ldmatrix.sync.aligned.m8n8.x4.shared.b16 {%0,%1,%2,%3}, [%4];"
        : "=r"(r[0]), "=r"(r[1]), "=r"(r[2]), "=r"(r[3]) : "r"(addr));
}
__device__ __forceinline__ void ldm_x4_t(uint32_t* r, uint32_t addr) {
    asm volatile("ldmatrix.sync.aligned.m8n8.x4.trans.shared.b16 {%0,%1,%2,%3}, [%4];"
        : "=r"(r[0]), "=r"(r[1]), "=r"(r[2]), "=r"(r[3]) : "r"(addr));
}
__device__ __forceinline__ void mma_f16(float* c, const uint32_t* a, const uint32_t* b) {
    asm volatile("mma.sync.aligned.m16n8k16.row.col.f32.f16.f16.f32 "
        "{%0,%1,%2,%3}, {%4,%5,%6,%7}, {%8,%9}, {%0,%1,%2,%3};\n"
        : "+f"(c[0]), "+f"(c[1]), "+f"(c[2]), "+f"(c[3])
        : "r"(a[0]), "r"(a[1]), "r"(a[2]), "r"(a[3]), "r"(b[0]), "r"(b[1]));
}
__device__ __forceinline__ uint32_t pack_h2(float a, float b) {
    __half2 h = __floats2half2_rn(a, b);
    return *(uint32_t*)&h;
}
__device__ __forceinline__ float fexp2(float x) {
    float y;
    asm("ex2.approx.f32 %0, %1;" : "=f"(y) : "f"(x));
    return y;
}

// ============================================================
// prep: cvt x, cvt weights, rope table — one launch
// ============================================================
__global__ void __launch_bounds__(256)
prep_kernel(const float* __restrict__ x,
            const float* __restrict__ Wq, const float* __restrict__ Wk,
            const float* __restrict__ Wv, const float* __restrict__ Wc)
{
    const int bid = blockIdx.x;
    const int tid = threadIdx.x;
    if (bid < 4096) {
        int i = bid * 256 + tid;
        float4 v = ((const float4*)x)[i];
        ((uint32_t*)g_xf)[2*i]   = pack_h2(v.x, v.y);
        ((uint32_t*)g_xf)[2*i+1] = pack_h2(v.z, v.w);
    } else if (bid < 7168) {
        int i = (bid - 4096) * 256 + tid;
        const float* src; int off;
        if      (i < 262144) { src = Wq; off = i; }
        else if (i < 393216) { src = Wk; off = i - 262144; }
        else if (i < 524288) { src = Wv; off = i - 393216; }
        else                 { src = Wc; off = i - 524288; }
        float4 v = ((const float4*)src)[off];
        ((uint32_t*)g_wf)[2*i]   = pack_h2(v.x, v.y);
        ((uint32_t*)g_wf)[2*i+1] = pack_h2(v.z, v.w);
    } else {
        int t = (bid - 7168) * 4 + (tid >> 6);
        int c = tid & 63;
        int j = c & 31;
        double inv = pow(10000.0, -(double)j / 32.0);
        float  ang = (float)t * (float)inv;
        double s, cc;
        sincos((double)ang, &s, &cc);
        g_cos[t * DH + c] = (float)cc;
        g_sin[t * DH + c] = (float)s;
    }
}

// ============================================================
// fp16 HMMA GEMM (R8-validated): K-chunk 32, 3-stage single-sync
// pipeline, 2 CTAs/SM. A:[M,K] fp16, W:[N,K] fp16 (K-contig).
// ============================================================
#define GS_ROWB   80
#define GS_MAT    (128 * GS_ROWB)       // 10240
#define GS_STAGE  (2 * GS_MAT)          // 20480 (A, B)
#define GS_SMEM   (3 * GS_STAGE)        // 61440 -> 2 CTAs/SM

__device__ __forceinline__ void hgemm_load_chunk(
    const __half* __restrict__ A, const __half* __restrict__ B,
    int K, int bm, int bn, int k0, uint32_t sbase, int tid)
{
#pragma unroll
    for (int i = 0; i < 4; i++) {
        int task = tid + (i << 8);      // 1024: op(2) x row(128) x granule(4)
        int op   = task >> 9;
        int t2   = task & 511;
        int row  = t2 >> 2;
        int g    = t2 & 3;
        const __half* base = op ? B : A;
        int grow = (op ? bn : bm) + row;
        const void* src = base + (size_t)grow * K + k0 + (g << 3);
        uint32_t dst = sbase + op * GS_MAT + row * GS_ROWB + (g << 4);
        cp16(dst, src);
    }
}

__device__ __forceinline__ void hgemm_body(
    const __half* __restrict__ A, const __half* __restrict__ B,
    float* __restrict__ C, int K, int N, int bm, int bn, int mode)
{
    extern __shared__ __align__(128) char sm[];
    const uint32_t smb = smem_u32(sm);
    const int tid  = threadIdx.x;
    const int wid  = tid >> 5;
    const int lane = tid & 31;
    const int wm = (wid >> 2) << 6;
    const int wn = (wid & 3) << 5;

    const int rA = (lane & 7) + ((lane >> 3) & 1) * 8;
    const int cA = (lane >> 4) << 3;
    const int rB = (lane & 7) + ((lane >> 4) << 3);
    const int cB = ((lane >> 3) & 1) << 3;

    float acc[4][4][4];
#pragma unroll
    for (int mt = 0; mt < 4; mt++)
#pragma unroll
        for (int nt = 0; nt < 4; nt++)
#pragma unroll
            for (int e = 0; e < 4; e++) acc[mt][nt][e] = 0.f;

    const int NC = K >> 5;              // chunks of 32

    hgemm_load_chunk(A, B, K, bm, bn, 0, smb, tid);
    cp_commit();
    hgemm_load_chunk(A, B, K, bm, bn, 32, smb + GS_STAGE, tid);
    cp_commit();

    int bc = 0, bp = 2;
    for (int c = 0; c < NC; c++) {
        cp_wait<1>();
        __syncthreads();
        if (c + 2 < NC)
            hgemm_load_chunk(A, B, K, bm, bn, (c + 2) << 5,
                             smb + bp * GS_STAGE, tid);
        cp_commit();
        const uint32_t sb = smb + bc * GS_STAGE;
        bc = (bc == 2) ? 0 : bc + 1;
        bp = (bp == 2) ? 0 : bp + 1;

#pragma unroll
        for (int ks = 0; ks < 2; ks++) {
            const int k0 = ks << 4;
            uint32_t af[4][4], bf[2][4];
#pragma unroll
            for (int mt = 0; mt < 4; mt++) {
                uint32_t ro = (uint32_t)(wm + (mt << 4) + rA) * GS_ROWB + ((k0 + cA) << 1);
                ldm_x4(af[mt], sb + ro);
            }
#pragma unroll
            for (int nt2 = 0; nt2 < 2; nt2++) {
                uint32_t ro = (uint32_t)(wn + (nt2 << 4) + rB) * GS_ROWB + ((k0 + cB) << 1);
                ldm_x4(bf[nt2], sb + GS_MAT + ro);
            }
#pragma unroll
            for (int mt = 0; mt < 4; mt++)
#pragma unroll
                for (int nt = 0; nt < 4; nt++)
                    mma_f16(acc[mt][nt], af[mt], &bf[nt >> 1][(nt & 1) << 1]);
        }
    }

    const int g  = lane >> 2;
    const int tg = lane & 3;
    if (mode == 0) {
#pragma unroll
        for (int mt = 0; mt < 4; mt++) {
            const int row0 = bm + wm + (mt << 4) + g;
#pragma unroll
            for (int nt = 0; nt < 4; nt++) {
                const int col = bn + wn + (nt << 3) + (tg << 1);
                *(float2*)&C[(size_t)row0 * N + col] =
                    make_float2(acc[mt][nt][0], acc[mt][nt][1]);
                *(float2*)&C[(size_t)(row0 + 8) * N + col] =
                    make_float2(acc[mt][nt][2], acc[mt][nt][3]);
            }
        }
    } else {
        // rope + QSCALE -> g_qf (fp16), scores end up in log2 domain
#pragma unroll
        for (int mt = 0; mt < 4; mt++) {
            const int row0 = bm + wm + (mt << 4) + g;
            const int t0 = row0 & (T_ - 1);
            const int t1 = (row0 + 8) & (T_ - 1);
#pragma unroll
            for (int nt = 0; nt < 4; nt++) {
                const int col = bn + wn + (nt << 3) + (tg << 1);
                const int d0 = col & 63, d1 = d0 + 1;
                float q0 = acc[mt][nt][0] * QSCALE, q1 = acc[mt][nt][1] * QSCALE;
                float c0 = g_cos[t0*DH+d0], s0 = g_sin[t0*DH+d0];
                float c1 = g_cos[t0*DH+d1], s1 = g_sin[t0*DH+d1];
                ((uint32_t*)g_qf)[((size_t)row0 * CDIM + col) >> 1] =
                    pack_h2(q0*c0 - q1*s0, q1*c1 + q0*s1);
                q0 = acc[mt][nt][2] * QSCALE; q1 = acc[mt][nt][3] * QSCALE;
                c0 = g_cos[t1*DH+d0]; s0 = g_sin[t1*DH+d0];
                c1 = g_cos[t1*DH+d1]; s1 = g_sin[t1*DH+d1];
                ((uint32_t*)g_qf)[((size_t)(row0 + 8) * CDIM + col) >> 1] =
                    pack_h2(q0*c0 - q1*s0, q1*c1 + q0*s1);
            }
        }
    }
}

__global__ void __launch_bounds__(256, 2)
proj_gemm(const __half* __restrict__ xf, const __half* __restrict__ wf,
          float* __restrict__ Ck, float* __restrict__ Cv)
{
    const int bm = blockIdx.y << 7;
    if (blockIdx.z == 0) {
        hgemm_body(xf, wf + WQ_OFF, nullptr, CDIM, CDIM, bm, blockIdx.x << 7, 1);
    } else if (blockIdx.x < 4) {
        hgemm_body(xf, wf + WK_OFF, Ck, CDIM, 512, bm, blockIdx.x << 7, 0);
    } else {
        hgemm_body(xf, wf + WV_OFF, Cv, CDIM, 512, bm, (blockIdx.x - 4) << 7, 0);
    }
}

__global__ void __launch_bounds__(256, 2)
hgemm_wc(const __half* __restrict__ A, const __half* __restrict__ B,
         float* __restrict__ C)
{
    hgemm_body(A, B, C, CDIM, CDIM, blockIdx.y << 7, blockIdx.x << 7, 0);
}

// ============================================================
// Up-projection + RoPE for k, v -> fp16. 4 tokens per CTA.
// ============================================================
__global__ void __launch_bounds__(256)
upproj_rope_kernel(const float* __restrict__ klat, const float* __restrict__ vlat,
                   const float* __restrict__ Wku,  const float* __restrict__ Wvu)
{
    const int bt0 = blockIdx.x << 2;
    __shared__ float skl[2048], svl[2048];
    __shared__ float swk[64 * 33], swv[64 * 33];
    const int tid = threadIdx.x;

    for (int u = tid; u < 512; u += 256) {
        ((float4*)skl)[u] = ((const float4*)(klat + (size_t)bt0 * 512))[u];
        ((float4*)svl)[u] = ((const float4*)(vlat + (size_t)bt0 * 512))[u];
    }
    for (int i = tid; i < 64 * 32; i += 256) {
        int d = i >> 5, l = i & 31;
        swk[d * 33 + l] = Wku[i];
        swv[d * 33 + l] = Wvu[i];
    }
    __syncthreads();

#pragma unroll
    for (int u = 0; u < 8; u++) {
        const int unit = tid + (u << 8);
        const int tok = unit >> 9;
        const int p   = unit & 511;
        const int h  = p >> 5, i = p & 31;
        const int d0 = i << 1, d1 = d0 + 1;
        const int bt = bt0 + tok;
        const int t  = bt & (T_ - 1);
        const float* kl  = &skl[(tok << 9) + (h << 5)];
        const float* vl  = &svl[(tok << 9) + (h << 5)];
        const float* wk0 = &swk[d0 * 33];
        const float* wk1 = &swk[d1 * 33];
        const float* wv0 = &swv[d0 * 33];
        const float* wv1 = &swv[d1 * 33];
        float k0 = 0.f, k1 = 0.f, v0 = 0.f, v1 = 0.f;
#pragma unroll
        for (int l = 0; l < 32; l++) {
            float klv = kl[l], vlv = vl[l];
            k0 = fmaf(klv, wk0[l], k0);
            k1 = fmaf(klv, wk1[l], k1);
            v0 = fmaf(vlv, wv0[l], v0);
            v1 = fmaf(vlv, wv1[l], v1);
        }
        const float c0 = g_cos[t * DH + d0], s0 = g_sin[t * DH + d0];
        const float c1 = g_cos[t * DH + d1], s1 = g_sin[t * DH + d1];
        const size_t pi = (((size_t)bt * H_ + h) * DH + d0) >> 1;
        ((uint32_t*)g_kf)[pi] = pack_h2(k0 * c0 - k1 * s0, k1 * c1 + k0 * s1);
        ((uint32_t*)g_vf)[pi] = pack_h2(v0, v1);
    }
}

// ============================================================
// fp16 HMMA causal flash attention (R8-validated pipeline),
// softmax in log2 domain (q pre-scaled by log2e).
// ============================================================
#define AT_ROWB   144
#define AT_MAT    (64 * AT_ROWB)
#define AT_STAGE  (2 * AT_MAT)
#define AT_QOFF   (3 * AT_STAGE)
#define AT_QMAT   (128 * AT_ROWB)
#define AT_SMEM   (AT_QOFF + AT_QMAT)   // 73728

__device__ __forceinline__ void attn_load_kv(int b, int h, int kb,
                                             uint32_t sbase, int tid)
{
    const int k0 = kb << 6;
#pragma unroll
    for (int i = 0; i < 4; i++) {
        int task = tid + (i << 8);
        int op = task >> 9;
        int t2 = task & 511;
        int row = t2 >> 3, g = t2 & 7;
        const __half* base = op ? g_vf : g_kf;
        const void* src = base + ((size_t)(b * T_ + k0 + row) * H_ + h) * DH + (g << 3);
        cp16(sbase + op * AT_MAT + row * AT_ROWB + (g << 4), src);
    }
}

__global__ void __launch_bounds__(256, 2)
attn_mma_kernel()
{
    extern __shared__ __align__(128) char sm[];
    const uint32_t smb = smem_u32(sm);
    const int tid = threadIdx.x;
    const int wid = tid >> 5, lane = tid & 31;
    const int qt = gridDim.x - 1 - blockIdx.x;
    const int h = blockIdx.y, b = blockIdx.z;
    const int q0 = qt << 7;
    const int nkb = 2 * qt + 2;
    const int g = lane >> 2, tg = lane & 3;

#pragma unroll
    for (int i = 0; i < 4; i++) {
        int task = tid + (i << 8);
        int row = task >> 3, gg = task & 7;
        const void* src = g_qf + ((size_t)(b * T_ + q0 + row) * H_ + h) * DH + (gg << 3);
        cp16(smb + AT_QOFF + row * AT_ROWB + (gg << 4), src);
    }
    cp_commit();
    attn_load_kv(b, h, 0, smb, tid);
    cp_commit();
    attn_load_kv(b, h, 1, smb + AT_STAGE, tid);
    cp_commit();

    cp_wait<2>();
    __syncthreads();
    const int rA = (lane & 7) + ((lane >> 3) & 1) * 8;
    const int cA = (lane >> 4) << 3;
    uint32_t qf[4][4];
#pragma unroll
    for (int kf = 0; kf < 4; kf++) {
        uint32_t ro = (uint32_t)(wid * 16 + rA) * AT_ROWB + ((kf * 16 + cA) << 1);
        ldm_x4(qf[kf], smb + AT_QOFF + ro);
    }

    const int rB = (lane & 7) + ((lane >> 4) << 3);
    const int cB = ((lane >> 3) & 1) << 3;
    const int rV = lane & 15;
    const int cV = (lane >> 4) << 4;

    float yacc[8][4];
#pragma unroll
    for (int i = 0; i < 8; i++)
#pragma unroll
        for (int e = 0; e < 4; e++) yacc[i][e] = 0.f;
    float m0 = -1e30f, m1 = -1e30f, l0 = 0.f, l1 = 0.f;

    int bc = 0, bp = 2;
    for (int kb = 0; kb < nkb; kb++) {
        cp_wait<1>();
        __syncthreads();
        if (kb + 2 < nkb)
            attn_load_kv(b, h, kb + 2, smb + bp * AT_STAGE, tid);
        cp_commit();
        const uint32_t sb = smb + bc * AT_STAGE;
        bc = (bc == 2) ? 0 : bc + 1;
        bp = (bp == 2) ? 0 : bp + 1;

        // ---- S = Q K^T  (scores already in log2 units) ----
        float s[8][4];
#pragma unroll
        for (int i = 0; i < 8; i++)
#pragma unroll
            for (int e = 0; e < 4; e++) s[i][e] = 0.f;
#pragma unroll
        for (int kf = 0; kf < 4; kf++) {
#pragma unroll
            for (int nt16 = 0; nt16 < 4; nt16++) {
                uint32_t ro = (uint32_t)(nt16 * 16 + rB) * AT_ROWB + ((kf * 16 + cB) << 1);
                uint32_t bk[4];
                ldm_x4(bk, sb + ro);
                mma_f16(s[nt16 * 2],     qf[kf], &bk[0]);
                mma_f16(s[nt16 * 2 + 1], qf[kf], &bk[2]);
            }
        }

        // ---- causal mask (diagonal blocks only) ----
        if (kb >= 2 * qt) {
            const int row0 = q0 + wid * 16 + g;
#pragma unroll
            for (int nt = 0; nt < 8; nt++) {
                const int col0 = (kb << 6) + nt * 8 + (tg << 1);
                if (col0     > row0)     s[nt][0] = -1e30f;
                if (col0 + 1 > row0)     s[nt][1] = -1e30f;
                if (col0     > row0 + 8) s[nt][2] = -1e30f;
                if (col0 + 1 > row0 + 8) s[nt][3] = -1e30f;
            }
        }

        // ---- online softmax (log2 domain, ex2.approx) ----
        float mx0 = -1e30f, mx1 = -1e30f;
#pragma unroll
        for (int nt = 0; nt < 8; nt++) {
            mx0 = fmaxf(mx0, fmaxf(s[nt][0], s[nt][1]));
            mx1 = fmaxf(mx1, fmaxf(s[nt][2], s[nt][3]));
        }
        mx0 = fmaxf(mx0, __shfl_xor_sync(0xffffffffu, mx0, 1));
        mx0 = fmaxf(mx0, __shfl_xor_sync(0xffffffffu, mx0, 2));
        mx1 = fmaxf(mx1, __shfl_xor_sync(0xffffffffu, mx1, 1));
        mx1 = fmaxf(mx1, __shfl_xor_sync(0xffffffffu, mx1, 2));
        const float mn0 = fmaxf(m0, mx0), mn1 = fmaxf(m1, mx1);
        const float a0 = fexp2(m0 - mn0), a1 = fexp2(m1 - mn1);
        m0 = mn0; m1 = mn1;
        float r0 = 0.f, r1 = 0.f;
#pragma unroll
        for (int nt = 0; nt < 8; nt++) {
            s[nt][0] = fexp2(s[nt][0] - mn0);
            s[nt][1] = fexp2(s[nt][1] - mn0);
            s[nt][2] = fexp2(s[nt][2] - mn1);
            s[nt][3] = fexp2(s[nt][3] - mn1);
            r0 += s[nt][0] + s[nt][1];
            r1 += s[nt][2] + s[nt][3];
        }
        r0 += __shfl_xor_sync(0xffffffffu, r0, 1);
        r0 += __shfl_xor_sync(0xffffffffu, r0, 2);
        r1 += __shfl_xor_sync(0xffffffffu, r1, 1);
        r1 += __shfl_xor_sync(0xffffffffu, r1, 2);
        l0 = l0 * a0 + r0;
        l1 = l1 * a1 + r1;
#pragma unroll
        for (int i = 0; i < 8; i++) {
            yacc[i][0] *= a0; yacc[i][1] *= a0;
            yacc[i][2] *= a1; yacc[i][3] *= a1;
        }

        // ---- O += P V ----
#pragma unroll
        for (int kf = 0; kf < 4; kf++) {
            uint32_t ph[4];
            ph[0] = pack_h2(s[2*kf][0],   s[2*kf][1]);
            ph[1] = pack_h2(s[2*kf][2],   s[2*kf][3]);
            ph[2] = pack_h2(s[2*kf+1][0], s[2*kf+1][1]);
            ph[3] = pack_h2(s[2*kf+1][2], s[2*kf+1][3]);
#pragma unroll
            for (int dt = 0; dt < 4; dt++) {
                uint32_t vh[4];
                uint32_t ro = (uint32_t)(kf * 16 + rV) * AT_ROWB + dt * 32 + cV;
                ldm_x4_t(vh, sb + AT_MAT + ro);
                mma_f16(yacc[dt * 2],     ph, &vh[0]);
                mma_f16(yacc[dt * 2 + 1], ph, &vh[2]);
            }
        }
    }

    // epilogue: fp16 y for Wc GEMM
    const float il0 = 1.f / l0, il1 = 1.f / l1;
    const int row0 = q0 + wid * 16 + g;
#pragma unroll
    for (int dt8 = 0; dt8 < 8; dt8++) {
        const int col = h * 64 + dt8 * 8 + (tg << 1);
        ((uint32_t*)g_yf)[((size_t)(b * T_ + row0) * CDIM + col) >> 1] =
            pack_h2(yacc[dt8][0] * il0, yacc[dt8][1] * il0);
        ((uint32_t*)g_yf)[((size_t)(b * T_ + row0 + 8) * CDIM + col) >> 1] =
            pack_h2(yacc[dt8][2] * il1, yacc[dt8][3] * il1);
    }
}

// ============================================================
// launch
// ============================================================
extern "C" void kernel_launch(void* const* d_in, const int* in_sizes, int n_in,
                              void* d_out, int out_size)
{
    const float* x   = (const float*)d_in[0];
    const float* Wq  = (const float*)d_in[1];
    const float* Wk  = (const float*)d_in[2];
    const float* Wv  = (const float*)d_in[3];
    const float* Wku = (const float*)d_in[4];
    const float* Wvu = (const float*)d_in[5];
    const float* Wc  = (const float*)d_in[6];

    float* out      = (float*)d_out;
    float* y_out    = out;
    float* klat_out = out + Y_ELEMS;
    float* vlat_out = out + Y_ELEMS + KL_ELEMS;

    __half *xf, *yf, *wf;
    cudaGetSymbolAddress((void**)&xf, g_xf);
    cudaGetSymbolAddress((void**)&yf, g_yf);
    cudaGetSymbolAddress((void**)&wf, g_wf);

    cudaFuncSetAttribute(attn_mma_kernel, cudaFuncAttributeMaxDynamicSharedMemorySize, AT_SMEM);
    cudaFuncSetAttribute(proj_gemm, cudaFuncAttributeMaxDynamicSharedMemorySize, GS_SMEM);
    cudaFuncSetAttribute(hgemm_wc, cudaFuncAttributeMaxDynamicSharedMemorySize, GS_SMEM);

    // 1. fused prep: cvt x, cvt weights, rope table
    prep_kernel<<<7680, 256>>>(x, Wq, Wk, Wv, Wc);

    // 2. projections (Wq w/ rope epilogue, k_lat, v_lat)
    dim3 gp(8, (B_ * T_) / 128, 2);
    proj_gemm<<<gp, 256, GS_SMEM>>>(xf, wf, klat_out, vlat_out);

    // 3. up-project + rope k/v
    upproj_rope_kernel<<<B_ * T_ / 4, 256>>>(klat_out, vlat_out, Wku, Wvu);

    // 4. flash attention
    dim3 ga(T_ / 128, H_, B_);
    attn_mma_kernel<<<ga, 256, AT_SMEM>>>();

    // 5. output projection
    dim3 gc(8, (B_ * T_) / 128);
    hgemm_wc<<<gc, 256, GS_SMEM>>>(yf, wf + WC_OFF, y_out);
}

// round 14
// speedup vs baseline: 1.1869x; 1.1869x over previous
#include <cuda_runtime.h>
#include <cuda_bf16.h>
#include <cuda_fp16.h>
#include <math.h>
#include <stdint.h>

#define B_   2
#define T_   2048
#define H_   16
#define DH   64
#define DL   32
#define CDIM 1024

#define Y_ELEMS  ((size_t)B_*T_*CDIM)
#define KL_ELEMS ((size_t)B_*T_*H_*DL)

// q pre-scale: (1/sqrt(64)) * log2(e)  -> softmax in log2 domain
#define QSCALE 0.1803368801111204f

// ---- scratch ----
__device__ float g_cos[T_*DH];
__device__ float g_sin[T_*DH];

__device__ __half g_xf[(size_t)B_*T_*CDIM];
__device__ __half g_yf[(size_t)B_*T_*CDIM];
__device__ __half g_qf[(size_t)B_*T_*H_*DH];
__device__ __half g_kf[(size_t)B_*T_*H_*DH];
__device__ __half g_vf[(size_t)B_*T_*H_*DH];
__device__ __half g_wf[3u*1024*1024];
#define WQ_OFF 0u
#define WK_OFF (1024u*1024u)
#define WV_OFF (1536u*1024u)
#define WC_OFF (2048u*1024u)

// ============================================================
// PTX helpers
// ============================================================
__device__ __forceinline__ uint32_t smem_u32(const void* p) {
    uint32_t a;
    asm("{ .reg .u64 t; cvta.to.shared.u64 t, %1; cvt.u32.u64 %0, t; }"
        : "=r"(a) : "l"(p));
    return a;
}
__device__ __forceinline__ void cp16(uint32_t dst, const void* src) {
    asm volatile("cp.async.cg.shared.global [%0], [%1], 16;\n"
                 :: "r"(dst), "l"(src));
}
__device__ __forceinline__ void cp_commit() {
    asm volatile("cp.async.commit_group;\n" ::: "memory");
}
template<int N> __device__ __forceinline__ void cp_wait() {
    asm volatile("cp.async.wait_group %0;\n" :: "n"(N) : "memory");
}
__device__ __forceinline__ void ldm_x4(uint32_t* r, uint32_t addr) {
    asm volatile("ldmatrix.sync.aligned.m8n8.x4.shared.b16 {%0,%1,%2,%3}, [%4];"
        : "=r"(r[0]), "=r"(r[1]), "=r"(r[2]), "=r"(r[3]) : "r"(addr));
}
__device__ __forceinline__ void ldm_x4_t(uint32_t* r, uint32_t addr) {
    asm volatile("ldmatrix.sync.aligned.m8n8.x4.trans.shared.b16 {%0,%1,%2,%3}, [%4];"
        : "=r"(r[0]), "=r"(r[1]), "=r"(r[2]), "=r"(r[3]) : "r"(addr));
}
__device__ __forceinline__ void mma_f16(float* c, const uint32_t* a, const uint32_t* b) {
    asm volatile("mma.sync.aligned.m16n8k16.row.col.f32.f16.f16.f32 "
        "{%0,%1,%2,%3}, {%4,%5,%6,%7}, {%8,%9}, {%0,%1,%2,%3};\n"
        : "+f"(c[0]), "+f"(c[1]), "+f"(c[2]), "+f"(c[3])
        : "r"(a[0]), "r"(a[1]), "r"(a[2]), "r"(a[3]), "r"(b[0]), "r"(b[1]));
}
__device__ __forceinline__ uint32_t pack_h2(float a, float b) {
    __half2 h = __floats2half2_rn(a, b);
    return *(uint32_t*)&h;
}
__device__ __forceinline__ float fexp2(float x) {
    float y;
    asm("ex2.approx.f32 %0, %1;" : "=f"(y) : "f"(x));
    return y;
}

// ============================================================
// prep kernels (R8-style separate launches)
// ============================================================
__global__ void __launch_bounds__(256)
cvt_x_kernel(const float* __restrict__ in)
{
    int i = blockIdx.x * blockDim.x + threadIdx.x;
    float4 v = ((const float4*)in)[i];
    ((uint32_t*)g_xf)[2*i]   = pack_h2(v.x, v.y);
    ((uint32_t*)g_xf)[2*i+1] = pack_h2(v.z, v.w);
}

__global__ void __launch_bounds__(256)
cvt_w_kernel(const float* __restrict__ Wq, const float* __restrict__ Wk,
             const float* __restrict__ Wv, const float* __restrict__ Wc)
{
    int i = blockIdx.x * blockDim.x + threadIdx.x;
    const float* src; int off;
    if      (i < 262144) { src = Wq; off = i; }
    else if (i < 393216) { src = Wk; off = i - 262144; }
    else if (i < 524288) { src = Wv; off = i - 393216; }
    else                 { src = Wc; off = i - 524288; }
    float4 v = ((const float4*)src)[off];
    ((uint32_t*)g_wf)[2*i]   = pack_h2(v.x, v.y);
    ((uint32_t*)g_wf)[2*i+1] = pack_h2(v.z, v.w);
}

// rope table: fp64 pow once per j per block; fp32 sincosf per element.
// 32 blocks x 256 threads; each block covers 64 t values.
__global__ void __launch_bounds__(256)
rope_table_kernel()
{
    __shared__ float sinv[32];
    const int tid = threadIdx.x;
    if (tid < 32)
        sinv[tid] = (float)pow(10000.0, -(double)tid / 32.0);
    __syncthreads();
    const int t0 = blockIdx.x << 6;
#pragma unroll
    for (int i = 0; i < 16; i++) {
        int idx = tid + (i << 8);          // 0..4095
        int t = t0 + (idx >> 6);
        int c = idx & 63;
        float ang = (float)t * sinv[c & 31];
        float s, cc;
        sincosf(ang, &s, &cc);
        g_cos[t * DH + c] = cc;
        g_sin[t * DH + c] = s;
    }
}

// ============================================================
// fp16 HMMA GEMM (R8-validated): K-chunk 32, 3-stage single-sync
// pipeline, 2 CTAs/SM.
// ============================================================
#define GS_ROWB   80
#define GS_MAT    (128 * GS_ROWB)       // 10240
#define GS_STAGE  (2 * GS_MAT)          // 20480 (A, B)
#define GS_SMEM   (3 * GS_STAGE)        // 61440

__device__ __forceinline__ void hgemm_load_chunk(
    const __half* __restrict__ A, const __half* __restrict__ B,
    int K, int bm, int bn, int k0, uint32_t sbase, int tid)
{
#pragma unroll
    for (int i = 0; i < 4; i++) {
        int task = tid + (i << 8);
        int op   = task >> 9;
        int t2   = task & 511;
        int row  = t2 >> 2;
        int g    = t2 & 3;
        const __half* base = op ? B : A;
        int grow = (op ? bn : bm) + row;
        const void* src = base + (size_t)grow * K + k0 + (g << 3);
        uint32_t dst = sbase + op * GS_MAT + row * GS_ROWB + (g << 4);
        cp16(dst, src);
    }
}

__device__ __forceinline__ void hgemm_body(
    const __half* __restrict__ A, const __half* __restrict__ B,
    float* __restrict__ C, int K, int N, int bm, int bn, int mode)
{
    extern __shared__ __align__(128) char sm[];
    const uint32_t smb = smem_u32(sm);
    const int tid  = threadIdx.x;
    const int wid  = tid >> 5;
    const int lane = tid & 31;
    const int wm = (wid >> 2) << 6;
    const int wn = (wid & 3) << 5;

    const int rA = (lane & 7) + ((lane >> 3) & 1) * 8;
    const int cA = (lane >> 4) << 3;
    const int rB = (lane & 7) + ((lane >> 4) << 3);
    const int cB = ((lane >> 3) & 1) << 3;

    float acc[4][4][4];
#pragma unroll
    for (int mt = 0; mt < 4; mt++)
#pragma unroll
        for (int nt = 0; nt < 4; nt++)
#pragma unroll
            for (int e = 0; e < 4; e++) acc[mt][nt][e] = 0.f;

    const int NC = K >> 5;

    hgemm_load_chunk(A, B, K, bm, bn, 0, smb, tid);
    cp_commit();
    hgemm_load_chunk(A, B, K, bm, bn, 32, smb + GS_STAGE, tid);
    cp_commit();

    int bc = 0, bp = 2;
    for (int c = 0; c < NC; c++) {
        cp_wait<1>();
        __syncthreads();
        if (c + 2 < NC)
            hgemm_load_chunk(A, B, K, bm, bn, (c + 2) << 5,
                             smb + bp * GS_STAGE, tid);
        cp_commit();
        const uint32_t sb = smb + bc * GS_STAGE;
        bc = (bc == 2) ? 0 : bc + 1;
        bp = (bp == 2) ? 0 : bp + 1;

#pragma unroll
        for (int ks = 0; ks < 2; ks++) {
            const int k0 = ks << 4;
            uint32_t af[4][4], bf[2][4];
#pragma unroll
            for (int mt = 0; mt < 4; mt++) {
                uint32_t ro = (uint32_t)(wm + (mt << 4) + rA) * GS_ROWB + ((k0 + cA) << 1);
                ldm_x4(af[mt], sb + ro);
            }
#pragma unroll
            for (int nt2 = 0; nt2 < 2; nt2++) {
                uint32_t ro = (uint32_t)(wn + (nt2 << 4) + rB) * GS_ROWB + ((k0 + cB) << 1);
                ldm_x4(bf[nt2], sb + GS_MAT + ro);
            }
#pragma unroll
            for (int mt = 0; mt < 4; mt++)
#pragma unroll
                for (int nt = 0; nt < 4; nt++)
                    mma_f16(acc[mt][nt], af[mt], &bf[nt >> 1][(nt & 1) << 1]);
        }
    }

    const int g  = lane >> 2;
    const int tg = lane & 3;
    if (mode == 0) {
#pragma unroll
        for (int mt = 0; mt < 4; mt++) {
            const int row0 = bm + wm + (mt << 4) + g;
#pragma unroll
            for (int nt = 0; nt < 4; nt++) {
                const int col = bn + wn + (nt << 3) + (tg << 1);
                *(float2*)&C[(size_t)row0 * N + col] =
                    make_float2(acc[mt][nt][0], acc[mt][nt][1]);
                *(float2*)&C[(size_t)(row0 + 8) * N + col] =
                    make_float2(acc[mt][nt][2], acc[mt][nt][3]);
            }
        }
    } else {
        // rope + QSCALE -> g_qf (fp16); scores land in log2 domain
#pragma unroll
        for (int mt = 0; mt < 4; mt++) {
            const int row0 = bm + wm + (mt << 4) + g;
            const int t0 = row0 & (T_ - 1);
            const int t1 = (row0 + 8) & (T_ - 1);
#pragma unroll
            for (int nt = 0; nt < 4; nt++) {
                const int col = bn + wn + (nt << 3) + (tg << 1);
                const int d0 = col & 63, d1 = d0 + 1;
                float q0 = acc[mt][nt][0] * QSCALE, q1 = acc[mt][nt][1] * QSCALE;
                float c0 = g_cos[t0*DH+d0], s0 = g_sin[t0*DH+d0];
                float c1 = g_cos[t0*DH+d1], s1 = g_sin[t0*DH+d1];
                ((uint32_t*)g_qf)[((size_t)row0 * CDIM + col) >> 1] =
                    pack_h2(q0*c0 - q1*s0, q1*c1 + q0*s1);
                q0 = acc[mt][nt][2] * QSCALE; q1 = acc[mt][nt][3] * QSCALE;
                c0 = g_cos[t1*DH+d0]; s0 = g_sin[t1*DH+d0];
                c1 = g_cos[t1*DH+d1]; s1 = g_sin[t1*DH+d1];
                ((uint32_t*)g_qf)[((size_t)(row0 + 8) * CDIM + col) >> 1] =
                    pack_h2(q0*c0 - q1*s0, q1*c1 + q0*s1);
            }
        }
    }
}

__global__ void __launch_bounds__(256, 2)
proj_gemm(const __half* __restrict__ xf, const __half* __restrict__ wf,
          float* __restrict__ Ck, float* __restrict__ Cv)
{
    const int bm = blockIdx.y << 7;
    if (blockIdx.z == 0) {
        hgemm_body(xf, wf + WQ_OFF, nullptr, CDIM, CDIM, bm, blockIdx.x << 7, 1);
    } else if (blockIdx.x < 4) {
        hgemm_body(xf, wf + WK_OFF, Ck, CDIM, 512, bm, blockIdx.x << 7, 0);
    } else {
        hgemm_body(xf, wf + WV_OFF, Cv, CDIM, 512, bm, (blockIdx.x - 4) << 7, 0);
    }
}

__global__ void __launch_bounds__(256, 2)
hgemm_wc(const __half* __restrict__ A, const __half* __restrict__ B,
         float* __restrict__ C)
{
    hgemm_body(A, B, C, CDIM, CDIM, blockIdx.y << 7, blockIdx.x << 7, 0);
}

// ============================================================
// Up-projection + RoPE for k, v -> fp16. 4 tokens per CTA.
// ============================================================
__global__ void __launch_bounds__(256)
upproj_rope_kernel(const float* __restrict__ klat, const float* __restrict__ vlat,
                   const float* __restrict__ Wku,  const float* __restrict__ Wvu)
{
    const int bt0 = blockIdx.x << 2;
    __shared__ float skl[2048], svl[2048];
    __shared__ float swk[64 * 33], swv[64 * 33];
    const int tid = threadIdx.x;

    for (int u = tid; u < 512; u += 256) {
        ((float4*)skl)[u] = ((const float4*)(klat + (size_t)bt0 * 512))[u];
        ((float4*)svl)[u] = ((const float4*)(vlat + (size_t)bt0 * 512))[u];
    }
    for (int i = tid; i < 64 * 32; i += 256) {
        int d = i >> 5, l = i & 31;
        swk[d * 33 + l] = Wku[i];
        swv[d * 33 + l] = Wvu[i];
    }
    __syncthreads();

#pragma unroll
    for (int u = 0; u < 8; u++) {
        const int unit = tid + (u << 8);
        const int tok = unit >> 9;
        const int p   = unit & 511;
        const int h  = p >> 5, i = p & 31;
        const int d0 = i << 1, d1 = d0 + 1;
        const int bt = bt0 + tok;
        const int t  = bt & (T_ - 1);
        const float* kl  = &skl[(tok << 9) + (h << 5)];
        const float* vl  = &svl[(tok << 9) + (h << 5)];
        const float* wk0 = &swk[d0 * 33];
        const float* wk1 = &swk[d1 * 33];
        const float* wv0 = &swv[d0 * 33];
        const float* wv1 = &swv[d1 * 33];
        float k0 = 0.f, k1 = 0.f, v0 = 0.f, v1 = 0.f;
#pragma unroll
        for (int l = 0; l < 32; l++) {
            float klv = kl[l], vlv = vl[l];
            k0 = fmaf(klv, wk0[l], k0);
            k1 = fmaf(klv, wk1[l], k1);
            v0 = fmaf(vlv, wv0[l], v0);
            v1 = fmaf(vlv, wv1[l], v1);
        }
        const float c0 = g_cos[t * DH + d0], s0 = g_sin[t * DH + d0];
        const float c1 = g_cos[t * DH + d1], s1 = g_sin[t * DH + d1];
        const size_t pi = (((size_t)bt * H_ + h) * DH + d0) >> 1;
        ((uint32_t*)g_kf)[pi] = pack_h2(k0 * c0 - k1 * s0, k1 * c1 + k0 * s1);
        ((uint32_t*)g_vf)[pi] = pack_h2(v0, v1);
    }
}

// ============================================================
// fp16 HMMA causal flash attention (R8 pipeline), log2 softmax,
// row-sum l computed via MMA against a ones fragment (no shfl).
// ============================================================
#define AT_ROWB   144
#define AT_MAT    (64 * AT_ROWB)
#define AT_STAGE  (2 * AT_MAT)
#define AT_QOFF   (3 * AT_STAGE)
#define AT_QMAT   (128 * AT_ROWB)
#define AT_SMEM   (AT_QOFF + AT_QMAT)   // 73728

__device__ __forceinline__ void attn_load_kv(int b, int h, int kb,
                                             uint32_t sbase, int tid)
{
    const int k0 = kb << 6;
#pragma unroll
    for (int i = 0; i < 4; i++) {
        int task = tid + (i << 8);
        int op = task >> 9;
        int t2 = task & 511;
        int row = t2 >> 3, g = t2 & 7;
        const __half* base = op ? g_vf : g_kf;
        const void* src = base + ((size_t)(b * T_ + k0 + row) * H_ + h) * DH + (g << 3);
        cp16(sbase + op * AT_MAT + row * AT_ROWB + (g << 4), src);
    }
}

__global__ void __launch_bounds__(256, 2)
attn_mma_kernel()
{
    extern __shared__ __align__(128) char sm[];
    const uint32_t smb = smem_u32(sm);
    const int tid = threadIdx.x;
    const int wid = tid >> 5, lane = tid & 31;
    const int qt = gridDim.x - 1 - blockIdx.x;
    const int h = blockIdx.y, b = blockIdx.z;
    const int q0 = qt << 7;
    const int nkb = 2 * qt + 2;
    const int g = lane >> 2, tg = lane & 3;

#pragma unroll
    for (int i = 0; i < 4; i++) {
        int task = tid + (i << 8);
        int row = task >> 3, gg = task & 7;
        const void* src = g_qf + ((size_t)(b * T_ + q0 + row) * H_ + h) * DH + (gg << 3);
        cp16(smb + AT_QOFF + row * AT_ROWB + (gg << 4), src);
    }
    cp_commit();
    attn_load_kv(b, h, 0, smb, tid);
    cp_commit();
    attn_load_kv(b, h, 1, smb + AT_STAGE, tid);
    cp_commit();

    cp_wait<2>();
    __syncthreads();
    const int rA = (lane & 7) + ((lane >> 3) & 1) * 8;
    const int cA = (lane >> 4) << 3;
    uint32_t qf[4][4];
#pragma unroll
    for (int kf = 0; kf < 4; kf++) {
        uint32_t ro = (uint32_t)(wid * 16 + rA) * AT_ROWB + ((kf * 16 + cA) << 1);
        ldm_x4(qf[kf], smb + AT_QOFF + ro);
    }

    const int rB = (lane & 7) + ((lane >> 4) << 3);
    const int cB = ((lane >> 3) & 1) << 3;
    const int rV = lane & 15;
    const int cV = (lane >> 4) << 4;

    const uint32_t ones2[2] = {0x3C003C00u, 0x3C003C00u};  // fp16 1.0 x4

    float yacc[8][4];
#pragma unroll
    for (int i = 0; i < 8; i++)
#pragma unroll
        for (int e = 0; e < 4; e++) yacc[i][e] = 0.f;
    float lacc[4] = {0.f, 0.f, 0.f, 0.f};   // l row-sum fragment (P @ ones)
    float m0 = -1e30f, m1 = -1e30f;

    int bc = 0, bp = 2;
    for (int kb = 0; kb < nkb; kb++) {
        cp_wait<1>();
        __syncthreads();
        if (kb + 2 < nkb)
            attn_load_kv(b, h, kb + 2, smb + bp * AT_STAGE, tid);
        cp_commit();
        const uint32_t sb = smb + bc * AT_STAGE;
        bc = (bc == 2) ? 0 : bc + 1;
        bp = (bp == 2) ? 0 : bp + 1;

        // ---- S = Q K^T (log2 units) ----
        float s[8][4];
#pragma unroll
        for (int i = 0; i < 8; i++)
#pragma unroll
            for (int e = 0; e < 4; e++) s[i][e] = 0.f;
#pragma unroll
        for (int kf = 0; kf < 4; kf++) {
#pragma unroll
            for (int nt16 = 0; nt16 < 4; nt16++) {
                uint32_t ro = (uint32_t)(nt16 * 16 + rB) * AT_ROWB + ((kf * 16 + cB) << 1);
                uint32_t bk[4];
                ldm_x4(bk, sb + ro);
                mma_f16(s[nt16 * 2],     qf[kf], &bk[0]);
                mma_f16(s[nt16 * 2 + 1], qf[kf], &bk[2]);
            }
        }

        // ---- causal mask (diagonal blocks only) ----
        if (kb >= 2 * qt) {
            const int row0 = q0 + wid * 16 + g;
#pragma unroll
            for (int nt = 0; nt < 8; nt++) {
                const int col0 = (kb << 6) + nt * 8 + (tg << 1);
                if (col0     > row0)     s[nt][0] = -1e30f;
                if (col0 + 1 > row0)     s[nt][1] = -1e30f;
                if (col0     > row0 + 8) s[nt][2] = -1e30f;
                if (col0 + 1 > row0 + 8) s[nt][3] = -1e30f;
            }
        }

        // ---- max (shfl over quad) ----
        float mx0 = -1e30f, mx1 = -1e30f;
#pragma unroll
        for (int nt = 0; nt < 8; nt++) {
            mx0 = fmaxf(mx0, fmaxf(s[nt][0], s[nt][1]));
            mx1 = fmaxf(mx1, fmaxf(s[nt][2], s[nt][3]));
        }
        mx0 = fmaxf(mx0, __shfl_xor_sync(0xffffffffu, mx0, 1));
        mx0 = fmaxf(mx0, __shfl_xor_sync(0xffffffffu, mx0, 2));
        mx1 = fmaxf(mx1, __shfl_xor_sync(0xffffffffu, mx1, 1));
        mx1 = fmaxf(mx1, __shfl_xor_sync(0xffffffffu, mx1, 2));
        const float mn0 = fmaxf(m0, mx0), mn1 = fmaxf(m1, mx1);
        const float a0 = fexp2(m0 - mn0), a1 = fexp2(m1 - mn1);
        m0 = mn0; m1 = mn1;

        // ---- exp2, rescale accumulators ----
#pragma unroll
        for (int nt = 0; nt < 8; nt++) {
            s[nt][0] = fexp2(s[nt][0] - mn0);
            s[nt][1] = fexp2(s[nt][1] - mn0);
            s[nt][2] = fexp2(s[nt][2] - mn1);
            s[nt][3] = fexp2(s[nt][3] - mn1);
        }
        lacc[0] *= a0; lacc[2] *= a1;
#pragma unroll
        for (int i = 0; i < 8; i++) {
            yacc[i][0] *= a0; yacc[i][1] *= a0;
            yacc[i][2] *= a1; yacc[i][3] *= a1;
        }

        // ---- pack P, accumulate l = P @ ones and O += P V ----
#pragma unroll
        for (int kf = 0; kf < 4; kf++) {
            uint32_t ph[4];
            ph[0] = pack_h2(s[2*kf][0],   s[2*kf][1]);
            ph[1] = pack_h2(s[2*kf][2],   s[2*kf][3]);
            ph[2] = pack_h2(s[2*kf+1][0], s[2*kf+1][1]);
            ph[3] = pack_h2(s[2*kf+1][2], s[2*kf+1][3]);
            mma_f16(lacc, ph, ones2);     // row sums, no shuffles
#pragma unroll
            for (int dt = 0; dt < 4; dt++) {
                uint32_t vh[4];
                uint32_t ro = (uint32_t)(kf * 16 + rV) * AT_ROWB + dt * 32 + cV;
                ldm_x4_t(vh, sb + AT_MAT + ro);
                mma_f16(yacc[dt * 2],     ph, &vh[0]);
                mma_f16(yacc[dt * 2 + 1], ph, &vh[2]);
            }
        }
    }

    // epilogue: fp16 y for Wc GEMM
    const float il0 = 1.f / lacc[0], il1 = 1.f / lacc[2];
    const int row0 = q0 + wid * 16 + g;
#pragma unroll
    for (int dt8 = 0; dt8 < 8; dt8++) {
        const int col = h * 64 + dt8 * 8 + (tg << 1);
        ((uint32_t*)g_yf)[((size_t)(b * T_ + row0) * CDIM + col) >> 1] =
            pack_h2(yacc[dt8][0] * il0, yacc[dt8][1] * il0);
        ((uint32_t*)g_yf)[((size_t)(b * T_ + row0 + 8) * CDIM + col) >> 1] =
            pack_h2(yacc[dt8][2] * il1, yacc[dt8][3] * il1);
    }
}

// ============================================================
// launch
// ============================================================
extern "C" void kernel_launch(void* const* d_in, const int* in_sizes, int n_in,
                              void* d_out, int out_size)
{
    const float* x   = (const float*)d_in[0];
    const float* Wq  = (const float*)d_in[1];
    const float* Wk  = (const float*)d_in[2];
    const float* Wv  = (const float*)d_in[3];
    const float* Wku = (const float*)d_in[4];
    const float* Wvu = (const float*)d_in[5];
    const float* Wc  = (const float*)d_in[6];

    float* out      = (float*)d_out;
    float* y_out    = out;
    float* klat_out = out + Y_ELEMS;
    float* vlat_out = out + Y_ELEMS + KL_ELEMS;

    __half *xf, *yf, *wf;
    cudaGetSymbolAddress((void**)&xf, g_xf);
    cudaGetSymbolAddress((void**)&yf, g_yf);
    cudaGetSymbolAddress((void**)&wf, g_wf);

    cudaFuncSetAttribute(attn_mma_kernel, cudaFuncAttributeMaxDynamicSharedMemorySize, AT_SMEM);
    cudaFuncSetAttribute(proj_gemm, cudaFuncAttributeMaxDynamicSharedMemorySize, GS_SMEM);
    cudaFuncSetAttribute(hgemm_wc, cudaFuncAttributeMaxDynamicSharedMemorySize, GS_SMEM);

    // 1. prep (R8-style separate launches; rope table optimized)
    rope_table_kernel<<<32, 256>>>();
    cvt_x_kernel<<<4096, 256>>>(x);
    cvt_w_kernel<<<3072, 256>>>(Wq, Wk, Wv, Wc);

    // 2. projections (Wq w/ rope epilogue, k_lat, v_lat)
    dim3 gp(8, (B_ * T_) / 128, 2);
    proj_gemm<<<gp, 256, GS_SMEM>>>(xf, wf, klat_out, vlat_out);

    // 3. up-project + rope k/v
    upproj_rope_kernel<<<B_ * T_ / 4, 256>>>(klat_out, vlat_out, Wku, Wvu);

    // 4. flash attention
    dim3 ga(T_ / 128, H_, B_);
    attn_mma_kernel<<<ga, 256, AT_SMEM>>>();

    // 5. output projection
    dim3 gc(8, (B_ * T_) / 128);
    hgemm_wc<<<gc, 256, GS_SMEM>>>(yf, wf + WC_OFF, y_out);
}

// round 17
// speedup vs baseline: 1.2535x; 1.0562x over previous
#include <cuda_runtime.h>
#include <cuda_bf16.h>
#include <cuda_fp16.h>
#include <math.h>
#include <stdint.h>

#define B_   2
#define T_   2048
#define H_   16
#define DH   64
#define DL   32
#define CDIM 1024

#define Y_ELEMS  ((size_t)B_*T_*CDIM)
#define KL_ELEMS ((size_t)B_*T_*H_*DL)

// q pre-scale: (1/sqrt(64)) * log2(e)  -> softmax in log2 domain
#define QSCALE 0.1803368801111204f

// ---- scratch ----
__device__ float g_cos[T_*DH];
__device__ float g_sin[T_*DH];

__device__ __half g_xf[(size_t)B_*T_*CDIM];
__device__ __half g_yf[(size_t)B_*T_*CDIM];
__device__ __half g_qf[(size_t)B_*T_*H_*DH];
__device__ __half g_kf[(size_t)B_*T_*H_*DH];
__device__ __half g_vf[(size_t)B_*T_*H_*DH];
__device__ __half g_wf[3u*1024*1024];
#define WQ_OFF 0u
#define WK_OFF (1024u*1024u)
#define WV_OFF (1536u*1024u)
#define WC_OFF (2048u*1024u)

// ============================================================
// PTX helpers
// ============================================================
__device__ __forceinline__ uint32_t smem_u32(const void* p) {
    uint32_t a;
    asm("{ .reg .u64 t; cvta.to.shared.u64 t, %1; cvt.u32.u64 %0, t; }"
        : "=r"(a) : "l"(p));
    return a;
}
__device__ __forceinline__ void cp16(uint32_t dst, const void* src) {
    asm volatile("cp.async.cg.shared.global [%0], [%1], 16;\n"
                 :: "r"(dst), "l"(src));
}
__device__ __forceinline__ void cp_commit() {
    asm volatile("cp.async.commit_group;\n" ::: "memory");
}
template<int N> __device__ __forceinline__ void cp_wait() {
    asm volatile("cp.async.wait_group %0;\n" :: "n"(N) : "memory");
}
__device__ __forceinline__ void ldm_x4(uint32_t* r, uint32_t addr) {
    asm volatile("ldmatrix.sync.aligned.m8n8.x4.shared.b16 {%0,%1,%2,%3}, [%4];"
        : "=r"(r[0]), "=r"(r[1]), "=r"(r[2]), "=r"(r[3]) : "r"(addr));
}
__device__ __forceinline__ void ldm_x4_t(uint32_t* r, uint32_t addr) {
    asm volatile("ldmatrix.sync.aligned.m8n8.x4.trans.shared.b16 {%0,%1,%2,%3}, [%4];"
        : "=r"(r[0]), "=r"(r[1]), "=r"(r[2]), "=r"(r[3]) : "r"(addr));
}
__device__ __forceinline__ void mma_f16(float* c, const uint32_t* a, const uint32_t* b) {
    asm volatile("mma.sync.aligned.m16n8k16.row.col.f32.f16.f16.f32 "
        "{%0,%1,%2,%3}, {%4,%5,%6,%7}, {%8,%9}, {%0,%1,%2,%3};\n"
        : "+f"(c[0]), "+f"(c[1]), "+f"(c[2]), "+f"(c[3])
        : "r"(a[0]), "r"(a[1]), "r"(a[2]), "r"(a[3]), "r"(b[0]), "r"(b[1]));
}
__device__ __forceinline__ uint32_t pack_h2(float a, float b) {
    __half2 h = __floats2half2_rn(a, b);
    return *(uint32_t*)&h;
}
__device__ __forceinline__ float fexp2(float x) {
    float y;
    asm("ex2.approx.f32 %0, %1;" : "=f"(y) : "f"(x));
    return y;
}

// ============================================================
// prep: merged fp32->fp16 converts (x + all weights)
// ============================================================
__global__ void __launch_bounds__(256)
prep_cvt_kernel(const float* __restrict__ x,
                const float* __restrict__ Wq, const float* __restrict__ Wk,
                const float* __restrict__ Wv, const float* __restrict__ Wc)
{
    const int bid = blockIdx.x;
    const int tid = threadIdx.x;
    if (bid < 4096) {
        int i = bid * 256 + tid;
        float4 v = ((const float4*)x)[i];
        ((uint32_t*)g_xf)[2*i]   = pack_h2(v.x, v.y);
        ((uint32_t*)g_xf)[2*i+1] = pack_h2(v.z, v.w);
    } else {
        int i = (bid - 4096) * 256 + tid;
        const float* src; int off;
        if      (i < 262144) { src = Wq; off = i; }
        else if (i < 393216) { src = Wk; off = i - 262144; }
        else if (i < 524288) { src = Wv; off = i - 393216; }
        else                 { src = Wc; off = i - 524288; }
        float4 v = ((const float4*)src)[off];
        ((uint32_t*)g_wf)[2*i]   = pack_h2(v.x, v.y);
        ((uint32_t*)g_wf)[2*i+1] = pack_h2(v.z, v.w);
    }
}

// rope table: fp64 pow once per j per block; fp32 sincosf per element.
__global__ void __launch_bounds__(256)
rope_table_kernel()
{
    __shared__ float sinv[32];
    const int tid = threadIdx.x;
    if (tid < 32)
        sinv[tid] = (float)pow(10000.0, -(double)tid / 32.0);
    __syncthreads();
    const int t0 = blockIdx.x << 6;
#pragma unroll
    for (int i = 0; i < 16; i++) {
        int idx = tid + (i << 8);
        int t = t0 + (idx >> 6);
        int c = idx & 63;
        float ang = (float)t * sinv[c & 31];
        float s, cc;
        sincosf(ang, &s, &cc);
        g_cos[t * DH + c] = cc;
        g_sin[t * DH + c] = s;
    }
}

// ============================================================
// fp16 HMMA GEMM (R8 pipeline): K-chunk 32, 3 stages, 2 CTAs/SM.
// modes: 0 = fp32 C store; 1 = rope+QSCALE -> g_qf;
//        2 = fp32 C + up-proj(Wu)+rope -> g_kf;
//        3 = fp32 C + up-proj(Wu)      -> g_vf.
// ============================================================
#define GS_ROWB   80
#define GS_MAT    (128 * GS_ROWB)       // 10240
#define GS_STAGE  (2 * GS_MAT)          // 20480 (A, B)
#define GS_SMEM   (3 * GS_STAGE)        // 61440

__device__ __forceinline__ void hgemm_load_chunk(
    const __half* __restrict__ A, const __half* __restrict__ B,
    int K, int bm, int bn, int k0, uint32_t sbase, int tid)
{
#pragma unroll
    for (int i = 0; i < 4; i++) {
        int task = tid + (i << 8);
        int op   = task >> 9;
        int t2   = task & 511;
        int row  = t2 >> 2;
        int g    = t2 & 3;
        const __half* base = op ? B : A;
        int grow = (op ? bn : bm) + row;
        const void* src = base + (size_t)grow * K + k0 + (g << 3);
        uint32_t dst = sbase + op * GS_MAT + row * GS_ROWB + (g << 4);
        cp16(dst, src);
    }
}

__device__ __forceinline__ void hgemm_body(
    const __half* __restrict__ A, const __half* __restrict__ B,
    float* __restrict__ C, int K, int N, int bm, int bn, int mode,
    const float* __restrict__ Wu)
{
    extern __shared__ __align__(128) char sm[];
    const uint32_t smb = smem_u32(sm);
    const int tid  = threadIdx.x;
    const int wid  = tid >> 5;
    const int lane = tid & 31;
    const int wm = (wid >> 2) << 6;
    const int wn = (wid & 3) << 5;

    const int rA = (lane & 7) + ((lane >> 3) & 1) * 8;
    const int cA = (lane >> 4) << 3;
    const int rB = (lane & 7) + ((lane >> 4) << 3);
    const int cB = ((lane >> 3) & 1) << 3;

    float acc[4][4][4];
#pragma unroll
    for (int mt = 0; mt < 4; mt++)
#pragma unroll
        for (int nt = 0; nt < 4; nt++)
#pragma unroll
            for (int e = 0; e < 4; e++) acc[mt][nt][e] = 0.f;

    const int NC = K >> 5;

    hgemm_load_chunk(A, B, K, bm, bn, 0, smb, tid);
    cp_commit();
    hgemm_load_chunk(A, B, K, bm, bn, 32, smb + GS_STAGE, tid);
    cp_commit();

    int bc = 0, bp = 2;
    for (int c = 0; c < NC; c++) {
        cp_wait<1>();
        __syncthreads();
        if (c + 2 < NC)
            hgemm_load_chunk(A, B, K, bm, bn, (c + 2) << 5,
                             smb + bp * GS_STAGE, tid);
        cp_commit();
        const uint32_t sb = smb + bc * GS_STAGE;
        bc = (bc == 2) ? 0 : bc + 1;
        bp = (bp == 2) ? 0 : bp + 1;

#pragma unroll
        for (int ks = 0; ks < 2; ks++) {
            const int k0 = ks << 4;
            uint32_t af[4][4], bf[2][4];
#pragma unroll
            for (int mt = 0; mt < 4; mt++) {
                uint32_t ro = (uint32_t)(wm + (mt << 4) + rA) * GS_ROWB + ((k0 + cA) << 1);
                ldm_x4(af[mt], sb + ro);
            }
#pragma unroll
            for (int nt2 = 0; nt2 < 2; nt2++) {
                uint32_t ro = (uint32_t)(wn + (nt2 << 4) + rB) * GS_ROWB + ((k0 + cB) << 1);
                ldm_x4(bf[nt2], sb + GS_MAT + ro);
            }
#pragma unroll
            for (int mt = 0; mt < 4; mt++)
#pragma unroll
                for (int nt = 0; nt < 4; nt++)
                    mma_f16(acc[mt][nt], af[mt], &bf[nt >> 1][(nt & 1) << 1]);
        }
    }

    const int g  = lane >> 2;
    const int tg = lane & 3;
    if (mode != 1) {
        // fp32 C store (modes 0, 2, 3)
#pragma unroll
        for (int mt = 0; mt < 4; mt++) {
            const int row0 = bm + wm + (mt << 4) + g;
#pragma unroll
            for (int nt = 0; nt < 4; nt++) {
                const int col = bn + wn + (nt << 3) + (tg << 1);
                *(float2*)&C[(size_t)row0 * N + col] =
                    make_float2(acc[mt][nt][0], acc[mt][nt][1]);
                *(float2*)&C[(size_t)(row0 + 8) * N + col] =
                    make_float2(acc[mt][nt][2], acc[mt][nt][3]);
            }
        }
    } else {
        // rope + QSCALE -> g_qf (fp16)
#pragma unroll
        for (int mt = 0; mt < 4; mt++) {
            const int row0 = bm + wm + (mt << 4) + g;
            const int t0 = row0 & (T_ - 1);
            const int t1 = (row0 + 8) & (T_ - 1);
#pragma unroll
            for (int nt = 0; nt < 4; nt++) {
                const int col = bn + wn + (nt << 3) + (tg << 1);
                const int d0 = col & 63, d1 = d0 + 1;
                float q0 = acc[mt][nt][0] * QSCALE, q1 = acc[mt][nt][1] * QSCALE;
                float c0 = g_cos[t0*DH+d0], s0 = g_sin[t0*DH+d0];
                float c1 = g_cos[t0*DH+d1], s1 = g_sin[t0*DH+d1];
                ((uint32_t*)g_qf)[((size_t)row0 * CDIM + col) >> 1] =
                    pack_h2(q0*c0 - q1*s0, q1*c1 + q0*s1);
                q0 = acc[mt][nt][2] * QSCALE; q1 = acc[mt][nt][3] * QSCALE;
                c0 = g_cos[t1*DH+d0]; s0 = g_sin[t1*DH+d0];
                c1 = g_cos[t1*DH+d1]; s1 = g_sin[t1*DH+d1];
                ((uint32_t*)g_qf)[((size_t)(row0 + 8) * CDIM + col) >> 1] =
                    pack_h2(q0*c0 - q1*s0, q1*c1 + q0*s1);
            }
        }
    }

    if (mode < 2) return;

    // ===== fused up-projection: out = acc(128x32/head) @ Wu^T, 4 heads/CTA =====
    // Load Wu (64x32 fp32) into smem as fp16, 80B row stride.
    __syncthreads();                    // all warps done with stage smem
    {
        int dh = tid >> 2, l0 = (tid & 3) << 3;   // 256 threads x 8 elems
        float4 va = *(const float4*)(Wu + dh * 32 + l0);
        float4 vb = *(const float4*)(Wu + dh * 32 + l0 + 4);
        uint4 pk = make_uint4(pack_h2(va.x, va.y), pack_h2(va.z, va.w),
                              pack_h2(vb.x, vb.y), pack_h2(vb.z, vb.w));
        *(uint4*)(sm + dh * GS_ROWB + (l0 << 1)) = pk;
    }
    __syncthreads();

    const int h = (bn + wn) >> 5;       // this warp's global head
    __half* dst = (mode == 2) ? g_kf : g_vf;

#pragma unroll
    for (int mt = 0; mt < 4; mt++) {
        // acc -> fp16 A fragments (K = 32 latent, two k16 blocks)
        uint32_t kf0[4], kf1[4];
        kf0[0] = pack_h2(acc[mt][0][0], acc[mt][0][1]);
        kf0[1] = pack_h2(acc[mt][0][2], acc[mt][0][3]);
        kf0[2] = pack_h2(acc[mt][1][0], acc[mt][1][1]);
        kf0[3] = pack_h2(acc[mt][1][2], acc[mt][1][3]);
        kf1[0] = pack_h2(acc[mt][2][0], acc[mt][2][1]);
        kf1[1] = pack_h2(acc[mt][2][2], acc[mt][2][3]);
        kf1[2] = pack_h2(acc[mt][3][0], acc[mt][3][1]);
        kf1[3] = pack_h2(acc[mt][3][2], acc[mt][3][3]);

        float o[8][4];
#pragma unroll
        for (int i = 0; i < 8; i++)
#pragma unroll
            for (int e = 0; e < 4; e++) o[i][e] = 0.f;

#pragma unroll
        for (int nt16 = 0; nt16 < 4; nt16++) {
            uint32_t bfr[4];
            ldm_x4(bfr, smb + (uint32_t)(nt16 * 16 + rB) * GS_ROWB + (cB << 1));
            mma_f16(o[nt16 * 2],     kf0, &bfr[0]);
            mma_f16(o[nt16 * 2 + 1], kf0, &bfr[2]);
            ldm_x4(bfr, smb + (uint32_t)(nt16 * 16 + rB) * GS_ROWB + ((16 + cB) << 1));
            mma_f16(o[nt16 * 2],     kf1, &bfr[0]);
            mma_f16(o[nt16 * 2 + 1], kf1, &bfr[2]);
        }

        const int row0 = bm + wm + (mt << 4) + g;     // global b*T+t row
        const int t0 = row0 & (T_ - 1);
        const int t1 = (row0 + 8) & (T_ - 1);
#pragma unroll
        for (int nt8 = 0; nt8 < 8; nt8++) {
            const int d0 = nt8 * 8 + (tg << 1), d1 = d0 + 1;
            float e0 = o[nt8][0], e1 = o[nt8][1];
            float e2 = o[nt8][2], e3 = o[nt8][3];
            if (mode == 2) {
                float c0 = g_cos[t0*DH+d0], s0 = g_sin[t0*DH+d0];
                float c1 = g_cos[t0*DH+d1], s1 = g_sin[t0*DH+d1];
                float r0 = e0*c0 - e1*s0, r1 = e1*c1 + e0*s1;
                e0 = r0; e1 = r1;
                c0 = g_cos[t1*DH+d0]; s0 = g_sin[t1*DH+d0];
                c1 = g_cos[t1*DH+d1]; s1 = g_sin[t1*DH+d1];
                r0 = e2*c0 - e3*s0; r1 = e3*c1 + e2*s1;
                e2 = r0; e3 = r1;
            }
            ((uint32_t*)dst)[(((size_t)row0 * H_ + h) * DH + d0) >> 1] =
                pack_h2(e0, e1);
            ((uint32_t*)dst)[(((size_t)(row0 + 8) * H_ + h) * DH + d0) >> 1] =
                pack_h2(e2, e3);
        }
    }
}

__global__ void __launch_bounds__(256, 2)
proj_gemm(const __half* __restrict__ xf, const __half* __restrict__ wf,
          float* __restrict__ Ck, float* __restrict__ Cv,
          const float* __restrict__ Wku, const float* __restrict__ Wvu)
{
    const int bm = blockIdx.y << 7;
    if (blockIdx.z == 0) {
        hgemm_body(xf, wf + WQ_OFF, nullptr, CDIM, CDIM, bm, blockIdx.x << 7, 1, nullptr);
    } else if (blockIdx.x < 4) {
        hgemm_body(xf, wf + WK_OFF, Ck, CDIM, 512, bm, blockIdx.x << 7, 2, Wku);
    } else {
        hgemm_body(xf, wf + WV_OFF, Cv, CDIM, 512, bm, (blockIdx.x - 4) << 7, 3, Wvu);
    }
}

__global__ void __launch_bounds__(256, 2)
hgemm_wc(const __half* __restrict__ A, const __half* __restrict__ B,
         float* __restrict__ C)
{
    hgemm_body(A, B, C, CDIM, CDIM, blockIdx.y << 7, blockIdx.x << 7, 0, nullptr);
}

// ============================================================
// fp16 HMMA causal flash attention (R14: log2 softmax, MMA rowsum)
// ============================================================
#define AT_ROWB   144
#define AT_MAT    (64 * AT_ROWB)
#define AT_STAGE  (2 * AT_MAT)
#define AT_QOFF   (3 * AT_STAGE)
#define AT_QMAT   (128 * AT_ROWB)
#define AT_SMEM   (AT_QOFF + AT_QMAT)   // 73728

__device__ __forceinline__ void attn_load_kv(int b, int h, int kb,
                                             uint32_t sbase, int tid)
{
    const int k0 = kb << 6;
#pragma unroll
    for (int i = 0; i < 4; i++) {
        int task = tid + (i << 8);
        int op = task >> 9;
        int t2 = task & 511;
        int row = t2 >> 3, g = t2 & 7;
        const __half* base = op ? g_vf : g_kf;
        const void* src = base + ((size_t)(b * T_ + k0 + row) * H_ + h) * DH + (g << 3);
        cp16(sbase + op * AT_MAT + row * AT_ROWB + (g << 4), src);
    }
}

__global__ void __launch_bounds__(256, 2)
attn_mma_kernel()
{
    extern __shared__ __align__(128) char sm[];
    const uint32_t smb = smem_u32(sm);
    const int tid = threadIdx.x;
    const int wid = tid >> 5, lane = tid & 31;
    const int qt = gridDim.x - 1 - blockIdx.x;
    const int h = blockIdx.y, b = blockIdx.z;
    const int q0 = qt << 7;
    const int nkb = 2 * qt + 2;
    const int g = lane >> 2, tg = lane & 3;

#pragma unroll
    for (int i = 0; i < 4; i++) {
        int task = tid + (i << 8);
        int row = task >> 3, gg = task & 7;
        const void* src = g_qf + ((size_t)(b * T_ + q0 + row) * H_ + h) * DH + (gg << 3);
        cp16(smb + AT_QOFF + row * AT_ROWB + (gg << 4), src);
    }
    cp_commit();
    attn_load_kv(b, h, 0, smb, tid);
    cp_commit();
    attn_load_kv(b, h, 1, smb + AT_STAGE, tid);
    cp_commit();

    cp_wait<2>();
    __syncthreads();
    const int rA = (lane & 7) + ((lane >> 3) & 1) * 8;
    const int cA = (lane >> 4) << 3;
    uint32_t qf[4][4];
#pragma unroll
    for (int kf = 0; kf < 4; kf++) {
        uint32_t ro = (uint32_t)(wid * 16 + rA) * AT_ROWB + ((kf * 16 + cA) << 1);
        ldm_x4(qf[kf], smb + AT_QOFF + ro);
    }

    const int rB = (lane & 7) + ((lane >> 4) << 3);
    const int cB = ((lane >> 3) & 1) << 3;
    const int rV = lane & 15;
    const int cV = (lane >> 4) << 4;

    const uint32_t ones2[2] = {0x3C003C00u, 0x3C003C00u};

    float yacc[8][4];
#pragma unroll
    for (int i = 0; i < 8; i++)
#pragma unroll
        for (int e = 0; e < 4; e++) yacc[i][e] = 0.f;
    float lacc[4] = {0.f, 0.f, 0.f, 0.f};
    float m0 = -1e30f, m1 = -1e30f;

    int bc = 0, bp = 2;
    for (int kb = 0; kb < nkb; kb++) {
        cp_wait<1>();
        __syncthreads();
        if (kb + 2 < nkb)
            attn_load_kv(b, h, kb + 2, smb + bp * AT_STAGE, tid);
        cp_commit();
        const uint32_t sb = smb + bc * AT_STAGE;
        bc = (bc == 2) ? 0 : bc + 1;
        bp = (bp == 2) ? 0 : bp + 1;

        float s[8][4];
#pragma unroll
        for (int i = 0; i < 8; i++)
#pragma unroll
            for (int e = 0; e < 4; e++) s[i][e] = 0.f;
#pragma unroll
        for (int kf = 0; kf < 4; kf++) {
#pragma unroll
            for (int nt16 = 0; nt16 < 4; nt16++) {
                uint32_t ro = (uint32_t)(nt16 * 16 + rB) * AT_ROWB + ((kf * 16 + cB) << 1);
                uint32_t bk[4];
                ldm_x4(bk, sb + ro);
                mma_f16(s[nt16 * 2],     qf[kf], &bk[0]);
                mma_f16(s[nt16 * 2 + 1], qf[kf], &bk[2]);
            }
        }

        if (kb >= 2 * qt) {
            const int row0 = q0 + wid * 16 + g;
#pragma unroll
            for (int nt = 0; nt < 8; nt++) {
                const int col0 = (kb << 6) + nt * 8 + (tg << 1);
                if (col0     > row0)     s[nt][0] = -1e30f;
                if (col0 + 1 > row0)     s[nt][1] = -1e30f;
                if (col0     > row0 + 8) s[nt][2] = -1e30f;
                if (col0 + 1 > row0 + 8) s[nt][3] = -1e30f;
            }
        }

        float mx0 = -1e30f, mx1 = -1e30f;
#pragma unroll
        for (int nt = 0; nt < 8; nt++) {
            mx0 = fmaxf(mx0, fmaxf(s[nt][0], s[nt][1]));
            mx1 = fmaxf(mx1, fmaxf(s[nt][2], s[nt][3]));
        }
        mx0 = fmaxf(mx0, __shfl_xor_sync(0xffffffffu, mx0, 1));
        mx0 = fmaxf(mx0, __shfl_xor_sync(0xffffffffu, mx0, 2));
        mx1 = fmaxf(mx1, __shfl_xor_sync(0xffffffffu, mx1, 1));
        mx1 = fmaxf(mx1, __shfl_xor_sync(0xffffffffu, mx1, 2));
        const float mn0 = fmaxf(m0, mx0), mn1 = fmaxf(m1, mx1);
        const float a0 = fexp2(m0 - mn0), a1 = fexp2(m1 - mn1);
        m0 = mn0; m1 = mn1;

#pragma unroll
        for (int nt = 0; nt < 8; nt++) {
            s[nt][0] = fexp2(s[nt][0] - mn0);
            s[nt][1] = fexp2(s[nt][1] - mn0);
            s[nt][2] = fexp2(s[nt][2] - mn1);
            s[nt][3] = fexp2(s[nt][3] - mn1);
        }
        lacc[0] *= a0; lacc[2] *= a1;
#pragma unroll
        for (int i = 0; i < 8; i++) {
            yacc[i][0] *= a0; yacc[i][1] *= a0;
            yacc[i][2] *= a1; yacc[i][3] *= a1;
        }

#pragma unroll
        for (int kf = 0; kf < 4; kf++) {
            uint32_t ph[4];
            ph[0] = pack_h2(s[2*kf][0],   s[2*kf][1]);
            ph[1] = pack_h2(s[2*kf][2],   s[2*kf][3]);
            ph[2] = pack_h2(s[2*kf+1][0], s[2*kf+1][1]);
            ph[3] = pack_h2(s[2*kf+1][2], s[2*kf+1][3]);
            mma_f16(lacc, ph, ones2);
#pragma unroll
            for (int dt = 0; dt < 4; dt++) {
                uint32_t vh[4];
                uint32_t ro = (uint32_t)(kf * 16 + rV) * AT_ROWB + dt * 32 + cV;
                ldm_x4_t(vh, sb + AT_MAT + ro);
                mma_f16(yacc[dt * 2],     ph, &vh[0]);
                mma_f16(yacc[dt * 2 + 1], ph, &vh[2]);
            }
        }
    }

    const float il0 = 1.f / lacc[0], il1 = 1.f / lacc[2];
    const int row0 = q0 + wid * 16 + g;
#pragma unroll
    for (int dt8 = 0; dt8 < 8; dt8++) {
        const int col = h * 64 + dt8 * 8 + (tg << 1);
        ((uint32_t*)g_yf)[((size_t)(b * T_ + row0) * CDIM + col) >> 1] =
            pack_h2(yacc[dt8][0] * il0, yacc[dt8][1] * il0);
        ((uint32_t*)g_yf)[((size_t)(b * T_ + row0 + 8) * CDIM + col) >> 1] =
            pack_h2(yacc[dt8][2] * il1, yacc[dt8][3] * il1);
    }
}

// ============================================================
// launch
// ============================================================
extern "C" void kernel_launch(void* const* d_in, const int* in_sizes, int n_in,
                              void* d_out, int out_size)
{
    const float* x   = (const float*)d_in[0];
    const float* Wq  = (const float*)d_in[1];
    const float* Wk  = (const float*)d_in[2];
    const float* Wv  = (const float*)d_in[3];
    const float* Wku = (const float*)d_in[4];
    const float* Wvu = (const float*)d_in[5];
    const float* Wc  = (const float*)d_in[6];

    float* out      = (float*)d_out;
    float* y_out    = out;
    float* klat_out = out + Y_ELEMS;
    float* vlat_out = out + Y_ELEMS + KL_ELEMS;

    __half *xf, *yf, *wf;
    cudaGetSymbolAddress((void**)&xf, g_xf);
    cudaGetSymbolAddress((void**)&yf, g_yf);
    cudaGetSymbolAddress((void**)&wf, g_wf);

    cudaFuncSetAttribute(attn_mma_kernel, cudaFuncAttributeMaxDynamicSharedMemorySize, AT_SMEM);
    cudaFuncSetAttribute(proj_gemm, cudaFuncAttributeMaxDynamicSharedMemorySize, GS_SMEM);
    cudaFuncSetAttribute(hgemm_wc, cudaFuncAttributeMaxDynamicSharedMemorySize, GS_SMEM);

    // 1. prep
    rope_table_kernel<<<32, 256>>>();
    prep_cvt_kernel<<<7168, 256>>>(x, Wq, Wk, Wv, Wc);

    // 2. projections: Wq(rope->g_qf), k_lat(+upproj+rope->g_kf), v_lat(+upproj->g_vf)
    dim3 gp(8, (B_ * T_) / 128, 2);
    proj_gemm<<<gp, 256, GS_SMEM>>>(xf, wf, klat_out, vlat_out, Wku, Wvu);

    // 3. flash attention
    dim3 ga(T_ / 128, H_, B_);
    attn_mma_kernel<<<ga, 256, AT_SMEM>>>();

    // 4. output projection
    dim3 gc(8, (B_ * T_) / 128);
    hgemm_wc<<<gc, 256, GS_SMEM>>>(yf, wf + WC_OFF, y_out);
}